// round 3
// baseline (speedup 1.0000x reference)
#include <cuda_runtime.h>
#include <cstdint>

// ---------------------------------------------------------------------------
// TSModel: 64-layer stacked LSTM over 64 timesteps, B=128, H=64.
// Systolic pipeline: 2 batch-groups x 64 layers = 128 persistent CTAs.
// CTA(g,l) keeps W_l in smem (gate-interleaved), c-state in registers,
// streams h up the layer stack through a global pipe with release/acquire flags.
// GEMM uses packed fma.rn.f32x2 (fp32x2) with a duplicated-A smem layout.
// ---------------------------------------------------------------------------

#define TT       64      // timesteps == layers
#define BFULL    128
#define HH       64
#define GG       2       // batch groups
#define BG       64      // batch per group
#define N4H      256     // 4*H
#define KDIM     128     // GEMM K (padded for layer 0)
#define NTHREADS 256

// [g][layer][t][h*BG + b]
__device__ float          g_pipe[GG][TT][TT][HH * BG];   // ~134 MB scratch
__device__ volatile int   g_flag[GG][TT][TT];
__device__ float          g_part[TT];

// smem: W_s = 128*256 f32 (128KB), A_dup = 128 rows x 64 float2 (64KB)
#define SMEM_BYTES ((KDIM * N4H + KDIM * BG * 2) * 4)

__device__ __forceinline__ void ffma2(unsigned long long& d,
                                      unsigned long long a,
                                      unsigned long long b) {
    asm volatile("fma.rn.f32x2 %0, %1, %2, %0;" : "+l"(d) : "l"(a), "l"(b));
}
__device__ __forceinline__ float lo32(unsigned long long v) {
    return __uint_as_float((unsigned)v);
}
__device__ __forceinline__ float hi32(unsigned long long v) {
    return __uint_as_float((unsigned)(v >> 32));
}
__device__ __forceinline__ float sigf(float x) {
    return __fdividef(1.f, 1.f + __expf(-x));
}
__device__ __forceinline__ float tanh_fast(float x) {
    return __fdividef(2.f, 1.f + __expf(-2.f * x)) - 1.f;
}

// ---------------------------------------------------------------------------
__global__ void zero_k() {
    int i = blockIdx.x * blockDim.x + threadIdx.x;
    if (i < GG * TT * TT) ((volatile int*)&g_flag[0][0][0])[i] = 0;
    if (i < TT) g_part[i] = 0.f;
}

// ---------------------------------------------------------------------------
__global__ __launch_bounds__(NTHREADS, 1)
void lstm_pipeline(const float* __restrict__ x,
                   const float* __restrict__ W0, const float* __restrict__ b0,
                   const float* __restrict__ Wl, const float* __restrict__ bl) {
    extern __shared__ float smem[];
    float*  W_s   = smem;                                   // [128][256] interleaved n'=h*4+g
    float2* A_dup = (float2*)(smem + KDIM * N4H);           // [128][64] duplicated pairs

    const int l   = blockIdx.x & 63;
    const int g   = blockIdx.x >> 6;
    const int tid = threadIdx.x;
    const int tm  = tid >> 5;   // 0..7  (M block of 8 rows)
    const int tn  = tid & 31;   // 0..31 (N' block of 8 = 2 h-cols x 4 gates)

    // ---- prologue: zero A (covers h(t=0)=0 + layer-0 K padding) ----
    for (int i = tid; i < KDIM * BG; i += NTHREADS)
        A_dup[i] = make_float2(0.f, 0.f);

    // ---- load weights once, gate-interleaved: n' = (n%64)*4 + n/64 ----
    if (l == 0) {
        for (int i = tid; i < KDIM * N4H; i += NTHREADS) W_s[i] = 0.f;
        __syncthreads();
        for (int i = tid; i < 65 * N4H; i += NTHREADS) {
            int k = i >> 8, n = i & 255;
            int np = ((n & 63) << 2) | (n >> 6);
            W_s[k * N4H + np] = W0[i];
        }
    } else {
        const float* Wsrc = Wl + (size_t)(l - 1) * KDIM * N4H;
        for (int i = tid; i < KDIM * N4H; i += NTHREADS) {
            int n = i & 255;
            int np = ((n & 63) << 2) | (n >> 6);
            W_s[(i & ~255) + np] = Wsrc[i];
        }
    }

    // ---- bias into registers (constant over t) ----
    float bias[8];
    {
        const float* bsrc = (l == 0) ? b0 : (bl + (l - 1) * N4H);
        #pragma unroll
        for (int j = 0; j < 8; j++) {
            int np = tn * 8 + j;
            int n = ((np & 3) << 6) | (np >> 2);  // back to original gate-major index
            bias[j] = bsrc[n];
        }
    }
    __syncthreads();

    const int ho_base = (l == 0) ? 1 : 64;   // A-row where h_own starts
    float c0[8], c1[8];
    #pragma unroll
    for (int i = 0; i < 8; i++) { c0[i] = 0.f; c1[i] = 0.f; }

    const float* pipe_in  = (l > 0) ? &g_pipe[g][l - 1][0][0] : nullptr;
    float*       pipe_out = &g_pipe[g][l][0][0];

    for (int t = 0; t < TT; t++) {
        // ---- acquire input ----
        if (l == 0) {
            if (tid < BG) {
                float v = x[(size_t)(g * BG + tid) * TT + t];
                A_dup[tid] = make_float2(v, v);      // A row 0 = x_t
            }
        } else {
            if (tid == 0) { while (g_flag[g][l - 1][t] == 0) { } }
            __syncthreads();
            __threadfence();
            const float* src = pipe_in + (size_t)t * (HH * BG);
            #pragma unroll
            for (int e = 0; e < (HH * BG) / NTHREADS; e++) {   // 16
                int idx = e * NTHREADS + tid;                  // idx = h*64 + m
                float v = src[idx];
                A_dup[idx] = make_float2(v, v);
            }
        }
        __syncthreads();

        // ---- GEMM: z[64][256'] = A[64][128] * W[128][256'], f32x2 packed ----
        unsigned long long acc[8][4];
        #pragma unroll
        for (int i = 0; i < 8; i++)
            #pragma unroll
            for (int p = 0; p < 4; p++) acc[i][p] = 0ull;

        #pragma unroll 4
        for (int k = 0; k < KDIM; k++) {
            const ulonglong2* ap = (const ulonglong2*)(A_dup + (k * BG + tm * 8));
            ulonglong2 av0 = ap[0], av1 = ap[1], av2 = ap[2], av3 = ap[3];
            const ulonglong2* bp = (const ulonglong2*)(W_s + (k * N4H + tn * 8));
            ulonglong2 bv0 = bp[0], bv1 = bp[1];
            unsigned long long a_[8] = {av0.x, av0.y, av1.x, av1.y,
                                        av2.x, av2.y, av3.x, av3.y};
            unsigned long long b_[4] = {bv0.x, bv0.y, bv1.x, bv1.y};
            #pragma unroll
            for (int mi = 0; mi < 8; mi++)
                #pragma unroll
                for (int p = 0; p < 4; p++)
                    ffma2(acc[mi][p], a_[mi], b_[p]);
        }

        // ---- gates + state update (all thread-local) ----
        float h2a[8], h2b[8];
        #pragma unroll
        for (int mi = 0; mi < 8; mi++) {
            float zi0 = lo32(acc[mi][0]) + bias[0];
            float zj0 = hi32(acc[mi][0]) + bias[1];
            float zf0 = lo32(acc[mi][1]) + bias[2];
            float zo0 = hi32(acc[mi][1]) + bias[3];
            float zi1 = lo32(acc[mi][2]) + bias[4];
            float zj1 = hi32(acc[mi][2]) + bias[5];
            float zf1 = lo32(acc[mi][3]) + bias[6];
            float zo1 = hi32(acc[mi][3]) + bias[7];
            c0[mi] = c0[mi] * sigf(zf0) + sigf(zi0) * tanh_fast(zj0);
            h2a[mi] = tanh_fast(c0[mi]) * sigf(zo0);
            c1[mi] = c1[mi] * sigf(zf1) + sigf(zi1) * tanh_fast(zj1);
            h2b[mi] = tanh_fast(c1[mi]) * sigf(zo1);
        }

        __syncthreads();   // all GEMM reads of A_dup done before h_own overwrite

        const int h0 = tn * 2, h1 = tn * 2 + 1;
        float* dst = pipe_out + (size_t)t * (HH * BG);
        #pragma unroll
        for (int mi = 0; mi < 8; mi++) {
            int m = tm * 8 + mi;
            A_dup[(ho_base + h0) * BG + m] = make_float2(h2a[mi], h2a[mi]);
            A_dup[(ho_base + h1) * BG + m] = make_float2(h2b[mi], h2b[mi]);
            dst[h0 * BG + m] = h2a[mi];
            dst[h1 * BG + m] = h2b[mi];
        }
        __threadfence();
        __syncthreads();
        if (tid == 0) g_flag[g][l][t] = 1;   // release
    }
}

// ---------------------------------------------------------------------------
// per-timestep dense + relu + partial squared-error sums
__global__ void dense_k(const float* __restrict__ labels,
                        const float* __restrict__ Wd,
                        const float* __restrict__ bd,
                        float* __restrict__ out, int out_size) {
    __shared__ float red[128];
    int t = blockIdx.x;
    int b = threadIdx.x;                 // 0..127
    int g = b >> 6, bl_ = b & 63;
    const float* ht = &g_pipe[g][TT - 1][t][0];
    float s = bd[t];
    #pragma unroll
    for (int h = 0; h < HH; h++)
        s += ht[h * BG + bl_] * __ldg(&Wd[t * HH + h]);
    float pred = fmaxf(s, 0.f);
    int oi = b * TT + t;
    if (oi < out_size) out[oi] = pred;
    float d = labels[oi] - pred;
    red[b] = d * d;
    __syncthreads();
    #pragma unroll
    for (int s2 = 64; s2 > 0; s2 >>= 1) {
        if (b < s2) red[b] += red[b + s2];
        __syncthreads();
    }
    if (b == 0) g_part[t] = red[0];
}

__global__ void loss_k(float* __restrict__ out, int out_size) {
    __shared__ float red[TT];
    int t = threadIdx.x;
    red[t] = g_part[t];
    __syncthreads();
    #pragma unroll
    for (int s = 32; s > 0; s >>= 1) {
        if (t < s) red[t] += red[t + s];
        __syncthreads();
    }
    if (t == 0 && out_size > BFULL * TT)
        out[BFULL * TT] = red[0] / (float)(BFULL * TT);
}

// ---------------------------------------------------------------------------
extern "C" void kernel_launch(void* const* d_in, const int* in_sizes, int n_in,
                              void* d_out, int out_size) {
    const float* x      = (const float*)d_in[0];
    const float* labels = (const float*)d_in[1];
    const float* W0     = (const float*)d_in[2];
    const float* b0     = (const float*)d_in[3];
    const float* Wl     = (const float*)d_in[4];
    const float* bl     = (const float*)d_in[5];
    const float* Wd     = (const float*)d_in[6];
    const float* bd     = (const float*)d_in[7];
    float* out = (float*)d_out;

    cudaFuncSetAttribute(lstm_pipeline,
                         cudaFuncAttributeMaxDynamicSharedMemorySize, SMEM_BYTES);

    zero_k<<<(GG * TT * TT + 255) / 256, 256>>>();
    lstm_pipeline<<<GG * TT, NTHREADS, SMEM_BYTES>>>(x, W0, b0, Wl, bl);
    dense_k<<<TT, 128>>>(labels, Wd, bd, out, out_size);
    loss_k<<<1, TT>>>(out, out_size);
}

// round 7
// speedup vs baseline: 1.4809x; 1.4809x over previous
#include <cuda_runtime.h>
#include <cuda_fp16.h>
#include <cstdint>

// ---------------------------------------------------------------------------
// TSModel: 64-layer stacked LSTM, T=64, B=128, H=64.
// 64 persistent CTAs (one per layer). Cell GEMM z[128][256]=A[128][128]@W^T
// via warp-level mma.sync m16n8k16 (f16 in, f32 acc), 3-product fp16 hi/lo
// split for fp32-quality results. Accumulators in registers -> epilogue reads
// gates directly (gate-permuted W columns put i,j,f,o of each cell in one
// thread). W resident in smem; c-state in registers; h handoff via L2 as
// packed half2(hi,lo) with flag release/acquire.
// ---------------------------------------------------------------------------

#define TT     64
#define BFULL  128
#define HH     64
#define N4H    256
#define NT     256

// smem: A_hi/A_lo 128x128 fp16 (32KB each), W_hi/W_lo 256x128 fp16 (64KB each)
#define SM_A_HI   0
#define SM_A_LO   32768
#define SM_W_HI   65536
#define SM_W_LO   131072
#define SM_BIAS   196608
#define SMEM_BYTES 197632

// [layer][t][m*64+h], element = packed u32: low16 = fp16 hi, high16 = fp16 lo
__device__ unsigned      g_pipe[TT][TT][BFULL * HH];
__device__ volatile int  g_flag[TT][TT];
__device__ float         g_part[TT];

// ---------------------------------------------------------------------------
__device__ __forceinline__ unsigned smem_u32(const void* p) {
    unsigned a;
    asm("{ .reg .u64 t; cvta.to.shared.u64 t, %1; cvt.u32.u64 %0, t; }"
        : "=r"(a) : "l"(p));
    return a;
}
__device__ __forceinline__ float sigf(float x) {
    return __fdividef(1.f, 1.f + __expf(-x));
}
__device__ __forceinline__ float tanh_fast(float x) {
    return __fdividef(2.f, 1.f + __expf(-2.f * x)) - 1.f;
}
__device__ __forceinline__ unsigned pack_hl(float v) {
    __half hi = __float2half_rn(v);
    __half lo = __float2half_rn(v - __half2float(hi));
    return (unsigned)__half_as_ushort(hi) | ((unsigned)__half_as_ushort(lo) << 16);
}
__device__ __forceinline__ float unpk(unsigned v) {
    return __half2float(__ushort_as_half((unsigned short)(v & 0xFFFF))) +
           __half2float(__ushort_as_half((unsigned short)(v >> 16)));
}
// column permutation: original n = g*64+h -> p so that one thread owns all 4
// gates of 4 h-values: p = (h>>4)*64 + ((h>>3)&1)*32 + g*8 + (h&7)
__device__ __host__ __forceinline__ int perm(int n) {
    int g = n >> 6, h = n & 63;
    return ((h >> 4) << 6) + (((h >> 3) & 1) << 5) + (g << 3) + (h & 7);
}
// swizzled tile offset: 256B rows, 16B chunks, chunk ^= row&7
__device__ __forceinline__ unsigned toff(int row, int k) {
    return (unsigned)(row * 256 + ((((k >> 3)) ^ (row & 7)) << 4) + (k & 7) * 2);
}

#define LDSM4(r, a) \
    asm volatile("ldmatrix.sync.aligned.m8n8.x4.shared.b16 {%0,%1,%2,%3}, [%4];" \
                 : "=r"((r)[0]), "=r"((r)[1]), "=r"((r)[2]), "=r"((r)[3]) \
                 : "r"(a))

#define MMA(c, a, b0, b1) \
    asm volatile("mma.sync.aligned.m16n8k16.row.col.f32.f16.f16.f32 " \
                 "{%0,%1,%2,%3},{%4,%5,%6,%7},{%8,%9},{%0,%1,%2,%3};" \
                 : "+f"((c)[0]), "+f"((c)[1]), "+f"((c)[2]), "+f"((c)[3]) \
                 : "r"((a)[0]), "r"((a)[1]), "r"((a)[2]), "r"((a)[3]), \
                   "r"(b0), "r"(b1))

// ---------------------------------------------------------------------------
__global__ void zero_k() {
    int i = blockIdx.x * blockDim.x + threadIdx.x;
    if (i < TT * TT) ((volatile int*)&g_flag[0][0])[i] = 0;
}

// ---------------------------------------------------------------------------
__global__ __launch_bounds__(NT, 1)
void lstm_hmma(const float* __restrict__ x,
               const float* __restrict__ W0, const float* __restrict__ b0,
               const float* __restrict__ Wl, const float* __restrict__ bl) {
    extern __shared__ char smem[];
    const unsigned sb = smem_u32(smem);
    const int l = blockIdx.x, tid = threadIdx.x;
    const int w = tid >> 5, lane = tid & 31;
    const int mi = w >> 2, ni = w & 3;          // warp tile: 64M x 64N
    const int gid = lane >> 2, tig = lane & 3;

    // ---- zero A tiles (and W tiles for l==0, K padding) ----
    {
        int zb = (l == 0) ? SM_BIAS : SM_W_HI;
        for (int i = tid * 16; i < zb; i += NT * 16)
            *(uint4*)(smem + i) = make_uint4(0, 0, 0, 0);
    }
    __syncthreads();

    // ---- weights -> fp16 hi/lo at permuted rows ----
    if (l == 0) {
        // W0[65][256]: row 0 (x) -> k=127; rows 1..64 (h_own) -> k=0..63
        for (int i = tid; i < 65 * N4H; i += NT) {
            int kw = i >> 8, n = i & 255;
            int k = kw ? (kw - 1) : 127;
            int p = perm(n);
            float f = W0[i];
            __half hi = __float2half_rn(f);
            __half lo = __float2half_rn(f - __half2float(hi));
            unsigned o = toff(p, k);
            *(__half*)(smem + SM_W_HI + o) = hi;
            *(__half*)(smem + SM_W_LO + o) = lo;
        }
    } else {
        const float* Ws = Wl + (size_t)(l - 1) * 128 * N4H;
        for (int i = tid; i < 128 * N4H; i += NT) {
            int k = i >> 8, n = i & 255;       // k: 0..63 h_in, 64..127 h_own
            int p = perm(n);
            float f = Ws[i];
            __half hi = __float2half_rn(f);
            __half lo = __float2half_rn(f - __half2float(hi));
            unsigned o = toff(p, k);
            *(__half*)(smem + SM_W_HI + o) = hi;
            *(__half*)(smem + SM_W_LO + o) = lo;
        }
    }
    {
        const float* bs = (l == 0) ? b0 : (bl + (size_t)(l - 1) * N4H);
        if (tid < N4H) *(float*)(smem + SM_BIAS + perm(tid) * 4) = bs[tid];
    }
    __syncthreads();

    // ---- ldmatrix per-lane address bases ----
    const unsigned aRow = (lane & 7) | (lane & 8);         // 0..15
    const unsigned aKp  = (lane >> 4) & 1;                 // +8k chunk
    const unsigned aSw  = aRow & 7;
    const unsigned bRow = (lane & 7) | ((lane & 16) >> 1); // 0..15
    const unsigned bKp  = (lane >> 3) & 1;
    const unsigned bSw  = bRow & 7;
    unsigned aBase[4], bBase[4];
    #pragma unroll
    for (int mt = 0; mt < 4; mt++)
        aBase[mt] = sb + SM_A_HI + (mi * 64 + mt * 16 + aRow) * 256;
    #pragma unroll
    for (int nb2 = 0; nb2 < 4; nb2++)
        bBase[nb2] = sb + SM_W_HI + (ni * 64 + nb2 * 16 + bRow) * 256;

    // ---- bias regs: bsv[nbh*8 + g*2 + u] ----
    float bsv[16];
    #pragma unroll
    for (int i = 0; i < 16; i++) {
        int nbh = i >> 3, g = (i >> 1) & 3, u = i & 1;
        bsv[i] = *(float*)(smem + SM_BIAS +
                           (ni * 64 + nbh * 32 + g * 8 + tig * 2 + u) * 4);
    }

    const int kown8 = (l == 0) ? 0 : 8;   // own-h chunk base (k/8)

    float cst[32];
    #pragma unroll
    for (int i = 0; i < 32; i++) cst[i] = 0.f;

    float xv = 0.f;
    if (l == 0 && tid < BFULL) xv = x[(size_t)tid * TT];

    for (int t = 0; t < TT; t++) {
        // ---- acquire + fill A ----
        if (l > 0) {
            if (tid == 0) { while (g_flag[l - 1][t] == 0) { } }
            __syncthreads();
            __threadfence();
            const int m = tid >> 1, ks32 = (tid & 1) * 32;
            const uint4* src = (const uint4*)&g_pipe[l - 1][t][m * HH + ks32];
            uint4 e[8];
            #pragma unroll
            for (int u = 0; u < 8; u++) e[u] = src[u];
            #pragma unroll
            for (int u = 0; u < 4; u++) {
                uint4 a = e[2 * u], b2 = e[2 * u + 1];
                uint4 hi4 = make_uint4(__byte_perm(a.x, a.y, 0x5410),
                                       __byte_perm(a.z, a.w, 0x5410),
                                       __byte_perm(b2.x, b2.y, 0x5410),
                                       __byte_perm(b2.z, b2.w, 0x5410));
                uint4 lo4 = make_uint4(__byte_perm(a.x, a.y, 0x7632),
                                       __byte_perm(a.z, a.w, 0x7632),
                                       __byte_perm(b2.x, b2.y, 0x7632),
                                       __byte_perm(b2.z, b2.w, 0x7632));
                int c = (ks32 >> 3) + u;               // h_in at k=0..63
                unsigned o = (unsigned)(m * 256 + ((c ^ (m & 7)) << 4));
                *(uint4*)(smem + SM_A_HI + o) = hi4;
                *(uint4*)(smem + SM_A_LO + o) = lo4;
            }
        } else {
            if (tid < BFULL) {
                __half hi = __float2half_rn(xv);
                __half lo = __float2half_rn(xv - __half2float(hi));
                unsigned o = toff(tid, 127);           // x at k=127
                *(__half*)(smem + SM_A_HI + o) = hi;
                *(__half*)(smem + SM_A_LO + o) = lo;
                if (t + 1 < TT) xv = x[(size_t)tid * TT + t + 1];
            }
        }
        __syncthreads();

        // ---- GEMM: 3-product fp16 split, HMMA m16n8k16 ----
        float acc[4][8][4];
        #pragma unroll
        for (int a2 = 0; a2 < 4; a2++)
            #pragma unroll
            for (int b2 = 0; b2 < 8; b2++)
                #pragma unroll
                for (int r2 = 0; r2 < 4; r2++) acc[a2][b2][r2] = 0.f;

        #pragma unroll
        for (int ks = 0; ks < 8; ks++) {
            unsigned af[4][4], wh[4][4], wl_[4][4];
            const unsigned koA = ((2 * ks + aKp) ^ aSw) << 4;
            const unsigned koB = ((2 * ks + bKp) ^ bSw) << 4;
            #pragma unroll
            for (int mt = 0; mt < 4; mt++) LDSM4(af[mt], aBase[mt] + koA);
            #pragma unroll
            for (int nb2 = 0; nb2 < 4; nb2++) {
                LDSM4(wh[nb2],  bBase[nb2] + koB);
                LDSM4(wl_[nb2], bBase[nb2] + 65536 + koB);
            }
            #pragma unroll
            for (int mt = 0; mt < 4; mt++)
                #pragma unroll
                for (int nb2 = 0; nb2 < 4; nb2++) {
                    MMA(acc[mt][2 * nb2],     af[mt], wh[nb2][0],  wh[nb2][1]);
                    MMA(acc[mt][2 * nb2 + 1], af[mt], wh[nb2][2],  wh[nb2][3]);
                    MMA(acc[mt][2 * nb2],     af[mt], wl_[nb2][0], wl_[nb2][1]);
                    MMA(acc[mt][2 * nb2 + 1], af[mt], wl_[nb2][2], wl_[nb2][3]);
                }
            #pragma unroll
            for (int mt = 0; mt < 4; mt++) LDSM4(af[mt], aBase[mt] + 32768 + koA);
            #pragma unroll
            for (int mt = 0; mt < 4; mt++)
                #pragma unroll
                for (int nb2 = 0; nb2 < 4; nb2++) {
                    MMA(acc[mt][2 * nb2],     af[mt], wh[nb2][0], wh[nb2][1]);
                    MMA(acc[mt][2 * nb2 + 1], af[mt], wh[nb2][2], wh[nb2][3]);
                }
        }

        // ---- epilogue: gates from register accumulators ----
        unsigned hAhi[16], hAlo[16];
        #pragma unroll
        for (int mt = 0; mt < 4; mt++)
            #pragma unroll
            for (int r2 = 0; r2 < 2; r2++)
                #pragma unroll
                for (int nbh = 0; nbh < 2; nbh++) {
                    const int idx = mt * 4 + r2 * 2 + nbh;
                    unsigned hp[2];
                    #pragma unroll
                    for (int u = 0; u < 2; u++) {
                        float zi = acc[mt][nbh * 4 + 0][r2 * 2 + u] + bsv[nbh * 8 + 0 + u];
                        float zj = acc[mt][nbh * 4 + 1][r2 * 2 + u] + bsv[nbh * 8 + 2 + u];
                        float zf = acc[mt][nbh * 4 + 2][r2 * 2 + u] + bsv[nbh * 8 + 4 + u];
                        float zo = acc[mt][nbh * 4 + 3][r2 * 2 + u] + bsv[nbh * 8 + 6 + u];
                        const int ci = idx * 2 + u;
                        float cn = cst[ci] * sigf(zf) + sigf(zi) * tanh_fast(zj);
                        cst[ci] = cn;
                        float h = tanh_fast(cn) * sigf(zo);
                        hp[u] = pack_hl(h);
                    }
                    const int m  = mi * 64 + mt * 16 + gid + 8 * r2;
                    const int h0 = ni * 16 + nbh * 8 + tig * 2;
                    *(uint2*)&g_pipe[l][t][m * HH + h0] = make_uint2(hp[0], hp[1]);
                    hAhi[idx] = __byte_perm(hp[0], hp[1], 0x5410);
                    hAlo[idx] = __byte_perm(hp[0], hp[1], 0x7632);
                }

        __syncthreads();   // all warps' GEMM smem reads complete

        // own-h recurrence into A (k = kown + h)
        #pragma unroll
        for (int mt = 0; mt < 4; mt++)
            #pragma unroll
            for (int r2 = 0; r2 < 2; r2++)
                #pragma unroll
                for (int nbh = 0; nbh < 2; nbh++) {
                    const int idx = mt * 4 + r2 * 2 + nbh;
                    const int m = mi * 64 + mt * 16 + gid + 8 * r2;
                    const int c = kown8 + ni * 2 + nbh;
                    unsigned o = (unsigned)(m * 256 + ((c ^ (m & 7)) << 4) + tig * 4);
                    *(unsigned*)(smem + SM_A_HI + o) = hAhi[idx];
                    *(unsigned*)(smem + SM_A_LO + o) = hAlo[idx];
                }

        __threadfence();
        __syncthreads();
        if (tid == 0) g_flag[l][t] = 1;   // release
    }
}

// ---------------------------------------------------------------------------
__global__ void dense_k(const float* __restrict__ labels,
                        const float* __restrict__ Wd,
                        const float* __restrict__ bd,
                        float* __restrict__ out, int out_size) {
    __shared__ float red[128];
    int t = blockIdx.x;
    int b = threadIdx.x;   // 0..127
    const unsigned* ht = &g_pipe[TT - 1][t][b * HH];
    float s = bd[t];
    #pragma unroll
    for (int h = 0; h < HH; h++)
        s += unpk(ht[h]) * __ldg(&Wd[t * HH + h]);
    float pred = fmaxf(s, 0.f);
    int oi = b * TT + t;
    if (oi < out_size) out[oi] = pred;
    float d = labels[oi] - pred;
    red[b] = d * d;
    __syncthreads();
    #pragma unroll
    for (int s2 = 64; s2 > 0; s2 >>= 1) {
        if (b < s2) red[b] += red[b + s2];
        __syncthreads();
    }
    if (b == 0) g_part[t] = red[0];
}

__global__ void loss_k(float* __restrict__ out, int out_size) {
    __shared__ float red[TT];
    int t = threadIdx.x;
    red[t] = g_part[t];
    __syncthreads();
    #pragma unroll
    for (int s = 32; s > 0; s >>= 1) {
        if (t < s) red[t] += red[t + s];
        __syncthreads();
    }
    if (t == 0 && out_size > BFULL * TT)
        out[BFULL * TT] = red[0] / (float)(BFULL * TT);
}

// ---------------------------------------------------------------------------
extern "C" void kernel_launch(void* const* d_in, const int* in_sizes, int n_in,
                              void* d_out, int out_size) {
    const float* x      = (const float*)d_in[0];
    const float* labels = (const float*)d_in[1];
    const float* W0     = (const float*)d_in[2];
    const float* b0     = (const float*)d_in[3];
    const float* Wl     = (const float*)d_in[4];
    const float* bl     = (const float*)d_in[5];
    const float* Wd     = (const float*)d_in[6];
    const float* bd     = (const float*)d_in[7];
    float* out = (float*)d_out;

    cudaFuncSetAttribute(lstm_hmma,
                         cudaFuncAttributeMaxDynamicSharedMemorySize, SMEM_BYTES);

    zero_k<<<(TT * TT + 255) / 256, 256>>>();
    lstm_hmma<<<TT, NT, SMEM_BYTES>>>(x, W0, b0, Wl, bl);
    dense_k<<<TT, 128>>>(labels, Wd, bd, out, out_size);
    loss_k<<<1, TT>>>(out, out_size);
}

// round 11
// speedup vs baseline: 2.7318x; 1.8447x over previous
#include <cuda_runtime.h>
#include <cuda_fp16.h>
#include <cstdint>

// ---------------------------------------------------------------------------
// TSModel: 64-layer stacked LSTM, T=64, B=128, H=64.
// 2 batch-groups x 64 layers = 128 persistent CTAs (one per (group, layer)).
// Cell GEMM z[64][256] = A[64][128] @ W^T via mma.sync m16n8k16 (f16 in,
// f32 acc), 3-product fp16 hi/lo split for fp32-quality results. Accumulators
// in registers; gate-permuted W columns put i,j,f,o of each cell in one
// thread. W resident in smem; c-state in registers; h handoff via L2 as
// packed half2(hi,lo) with flag release/acquire.
// ---------------------------------------------------------------------------

#define TT     64
#define BFULL  128
#define HH     64
#define GG     2
#define BG     64
#define N4H    256
#define NT     256

// smem: A_hi/A_lo 64x128 fp16 (16KB each), W_hi/W_lo 256x128 fp16 (64KB each)
#define SM_A_HI   0
#define SM_A_LO   16384
#define SM_W_HI   32768
#define SM_W_LO   98304
#define SM_BIAS   163840
#define SMEM_BYTES 164864

// [g][layer][t][m*64+h], element = packed u32: low16 = fp16 hi, high16 = lo
__device__ unsigned      g_pipe[GG][TT][TT][BG * HH];
__device__ volatile int  g_flag[GG][TT][TT];
__device__ float         g_part[TT];

// ---------------------------------------------------------------------------
__device__ __forceinline__ unsigned smem_u32(const void* p) {
    unsigned a;
    asm("{ .reg .u64 t; cvta.to.shared.u64 t, %1; cvt.u32.u64 %0, t; }"
        : "=r"(a) : "l"(p));
    return a;
}
__device__ __forceinline__ float sigf(float x) {
    return __fdividef(1.f, 1.f + __expf(-x));
}
__device__ __forceinline__ float tanh_fast(float x) {
    return __fdividef(2.f, 1.f + __expf(-2.f * x)) - 1.f;
}
__device__ __forceinline__ unsigned pack_hl(float v) {
    __half hi = __float2half_rn(v);
    __half lo = __float2half_rn(v - __half2float(hi));
    return (unsigned)__half_as_ushort(hi) | ((unsigned)__half_as_ushort(lo) << 16);
}
__device__ __forceinline__ float unpk(unsigned v) {
    return __half2float(__ushort_as_half((unsigned short)(v & 0xFFFF))) +
           __half2float(__ushort_as_half((unsigned short)(v >> 16)));
}
// column permutation: original n = g*64+h -> p so that one thread owns all 4
// gates of 4 h-values: p = (h>>4)*64 + ((h>>3)&1)*32 + g*8 + (h&7)
__device__ __host__ __forceinline__ int perm(int n) {
    int g = n >> 6, h = n & 63;
    return ((h >> 4) << 6) + (((h >> 3) & 1) << 5) + (g << 3) + (h & 7);
}
// swizzled tile offset: 256B rows, 16B chunks, chunk ^= row&7
__device__ __forceinline__ unsigned toff(int row, int k) {
    return (unsigned)(row * 256 + ((((k >> 3)) ^ (row & 7)) << 4) + (k & 7) * 2);
}

#define LDSM4(r, a) \
    asm volatile("ldmatrix.sync.aligned.m8n8.x4.shared.b16 {%0,%1,%2,%3}, [%4];" \
                 : "=r"((r)[0]), "=r"((r)[1]), "=r"((r)[2]), "=r"((r)[3]) \
                 : "r"(a))

#define MMA(c, a, b0, b1) \
    asm volatile("mma.sync.aligned.m16n8k16.row.col.f32.f16.f16.f32 " \
                 "{%0,%1,%2,%3},{%4,%5,%6,%7},{%8,%9},{%0,%1,%2,%3};" \
                 : "+f"((c)[0]), "+f"((c)[1]), "+f"((c)[2]), "+f"((c)[3]) \
                 : "r"((a)[0]), "r"((a)[1]), "r"((a)[2]), "r"((a)[3]), \
                   "r"(b0), "r"(b1))

// ---------------------------------------------------------------------------
__global__ void zero_k() {
    int i = blockIdx.x * blockDim.x + threadIdx.x;
    if (i < GG * TT * TT) ((volatile int*)&g_flag[0][0][0])[i] = 0;
}

// ---------------------------------------------------------------------------
__global__ __launch_bounds__(NT, 1)
void lstm_hmma(const float* __restrict__ x,
               const float* __restrict__ W0, const float* __restrict__ b0,
               const float* __restrict__ Wl, const float* __restrict__ bl) {
    extern __shared__ char smem[];
    const unsigned sb = smem_u32(smem);
    const int l = blockIdx.x & 63, g = blockIdx.x >> 6;
    const int tid = threadIdx.x;
    const int w = tid >> 5, lane = tid & 31;
    const int mi = w >> 2, ni = w & 3;          // warp tile: 32M x 64N
    const int gid = lane >> 2, tig = lane & 3;

    // ---- zero A tiles (and W tiles for l==0, K padding) ----
    {
        int zb = (l == 0) ? SM_BIAS : SM_W_HI;
        for (int i = tid * 16; i < zb; i += NT * 16)
            *(uint4*)(smem + i) = make_uint4(0, 0, 0, 0);
    }
    __syncthreads();

    // ---- weights -> fp16 hi/lo at permuted rows ----
    if (l == 0) {
        // W0[65][256]: row 0 (x) -> k=127; rows 1..64 (h_own) -> k=0..63
        for (int i = tid; i < 65 * N4H; i += NT) {
            int kw = i >> 8, n = i & 255;
            int k = kw ? (kw - 1) : 127;
            int p = perm(n);
            float f = W0[i];
            __half hi = __float2half_rn(f);
            __half lo = __float2half_rn(f - __half2float(hi));
            unsigned o = toff(p, k);
            *(__half*)(smem + SM_W_HI + o) = hi;
            *(__half*)(smem + SM_W_LO + o) = lo;
        }
    } else {
        const float* Ws = Wl + (size_t)(l - 1) * 128 * N4H;
        for (int i = tid; i < 128 * N4H; i += NT) {
            int k = i >> 8, n = i & 255;       // k: 0..63 h_in, 64..127 h_own
            int p = perm(n);
            float f = Ws[i];
            __half hi = __float2half_rn(f);
            __half lo = __float2half_rn(f - __half2float(hi));
            unsigned o = toff(p, k);
            *(__half*)(smem + SM_W_HI + o) = hi;
            *(__half*)(smem + SM_W_LO + o) = lo;
        }
    }
    {
        const float* bs = (l == 0) ? b0 : (bl + (size_t)(l - 1) * N4H);
        if (tid < N4H) *(float*)(smem + SM_BIAS + perm(tid) * 4) = bs[tid];
    }
    __syncthreads();

    // ---- ldmatrix per-lane address bases ----
    const unsigned aRow = (lane & 7) | (lane & 8);         // 0..15
    const unsigned aKp  = (lane >> 4) & 1;                 // +8k chunk
    const unsigned aSw  = aRow & 7;
    const unsigned bRow = (lane & 7) | ((lane & 16) >> 1); // 0..15
    const unsigned bKp  = (lane >> 3) & 1;
    const unsigned bSw  = bRow & 7;
    unsigned aBase[2], bBase[4];
    #pragma unroll
    for (int mt = 0; mt < 2; mt++)
        aBase[mt] = sb + SM_A_HI + (mi * 32 + mt * 16 + aRow) * 256;
    #pragma unroll
    for (int nb2 = 0; nb2 < 4; nb2++)
        bBase[nb2] = sb + SM_W_HI + (ni * 64 + nb2 * 16 + bRow) * 256;

    // ---- bias regs: bsv[nbh*8 + g*2 + u] ----
    float bsv[16];
    #pragma unroll
    for (int i = 0; i < 16; i++) {
        int nbh = i >> 3, gg = (i >> 1) & 3, u = i & 1;
        bsv[i] = *(float*)(smem + SM_BIAS +
                           (ni * 64 + nbh * 32 + gg * 8 + tig * 2 + u) * 4);
    }

    const int kown8 = (l == 0) ? 0 : 8;   // own-h chunk base (k/8)

    float cst[16];
    #pragma unroll
    for (int i = 0; i < 16; i++) cst[i] = 0.f;

    float xv = 0.f;
    if (l == 0 && tid < BG) xv = x[(size_t)(g * BG + tid) * TT];

    for (int t = 0; t < TT; t++) {
        // ---- acquire + fill A ----
        if (l > 0) {
            if (tid == 0) { while (g_flag[g][l - 1][t] == 0) { } }
            __syncthreads();
            __threadfence();
            const int m = tid >> 2, q = tid & 3;   // 16 cols per thread
            const uint4* src = (const uint4*)&g_pipe[g][l - 1][t][m * HH + q * 16];
            uint4 e[4];
            #pragma unroll
            for (int u = 0; u < 4; u++) e[u] = src[u];
            #pragma unroll
            for (int u = 0; u < 2; u++) {
                uint4 a = e[2 * u], b2 = e[2 * u + 1];
                uint4 hi4 = make_uint4(__byte_perm(a.x, a.y, 0x5410),
                                       __byte_perm(a.z, a.w, 0x5410),
                                       __byte_perm(b2.x, b2.y, 0x5410),
                                       __byte_perm(b2.z, b2.w, 0x5410));
                uint4 lo4 = make_uint4(__byte_perm(a.x, a.y, 0x7632),
                                       __byte_perm(a.z, a.w, 0x7632),
                                       __byte_perm(b2.x, b2.y, 0x7632),
                                       __byte_perm(b2.z, b2.w, 0x7632));
                int c = q * 2 + u;                     // h_in at k=0..63
                unsigned o = (unsigned)(m * 256 + ((c ^ (m & 7)) << 4));
                *(uint4*)(smem + SM_A_HI + o) = hi4;
                *(uint4*)(smem + SM_A_LO + o) = lo4;
            }
        } else {
            if (tid < BG) {
                __half hi = __float2half_rn(xv);
                __half lo = __float2half_rn(xv - __half2float(hi));
                unsigned o = toff(tid, 127);           // x at k=127
                *(__half*)(smem + SM_A_HI + o) = hi;
                *(__half*)(smem + SM_A_LO + o) = lo;
                if (t + 1 < TT) xv = x[(size_t)(g * BG + tid) * TT + t + 1];
            }
        }
        __syncthreads();

        // ---- GEMM: 3-product fp16 split, HMMA m16n8k16 ----
        float acc[2][8][4];
        #pragma unroll
        for (int a2 = 0; a2 < 2; a2++)
            #pragma unroll
            for (int b2 = 0; b2 < 8; b2++)
                #pragma unroll
                for (int r2 = 0; r2 < 4; r2++) acc[a2][b2][r2] = 0.f;

        #pragma unroll
        for (int ks = 0; ks < 8; ks++) {
            unsigned af[2][4], wh[4][4], wl_[4][4];
            const unsigned koA = ((2 * ks + aKp) ^ aSw) << 4;
            const unsigned koB = ((2 * ks + bKp) ^ bSw) << 4;
            #pragma unroll
            for (int mt = 0; mt < 2; mt++) LDSM4(af[mt], aBase[mt] + koA);
            #pragma unroll
            for (int nb2 = 0; nb2 < 4; nb2++) {
                LDSM4(wh[nb2],  bBase[nb2] + koB);
                LDSM4(wl_[nb2], bBase[nb2] + 65536 + koB);
            }
            #pragma unroll
            for (int mt = 0; mt < 2; mt++)
                #pragma unroll
                for (int nb2 = 0; nb2 < 4; nb2++) {
                    MMA(acc[mt][2 * nb2],     af[mt], wh[nb2][0],  wh[nb2][1]);
                    MMA(acc[mt][2 * nb2 + 1], af[mt], wh[nb2][2],  wh[nb2][3]);
                    MMA(acc[mt][2 * nb2],     af[mt], wl_[nb2][0], wl_[nb2][1]);
                    MMA(acc[mt][2 * nb2 + 1], af[mt], wl_[nb2][2], wl_[nb2][3]);
                }
            #pragma unroll
            for (int mt = 0; mt < 2; mt++) LDSM4(af[mt], aBase[mt] + 16384 + koA);
            #pragma unroll
            for (int mt = 0; mt < 2; mt++)
                #pragma unroll
                for (int nb2 = 0; nb2 < 4; nb2++) {
                    MMA(acc[mt][2 * nb2],     af[mt], wh[nb2][0], wh[nb2][1]);
                    MMA(acc[mt][2 * nb2 + 1], af[mt], wh[nb2][2], wh[nb2][3]);
                }
        }

        // ---- epilogue: gates from register accumulators ----
        unsigned hAhi[8], hAlo[8];
        #pragma unroll
        for (int mt = 0; mt < 2; mt++)
            #pragma unroll
            for (int r2 = 0; r2 < 2; r2++)
                #pragma unroll
                for (int nbh = 0; nbh < 2; nbh++) {
                    const int idx = mt * 4 + r2 * 2 + nbh;
                    unsigned hp[2];
                    #pragma unroll
                    for (int u = 0; u < 2; u++) {
                        float zi = acc[mt][nbh * 4 + 0][r2 * 2 + u] + bsv[nbh * 8 + 0 + u];
                        float zj = acc[mt][nbh * 4 + 1][r2 * 2 + u] + bsv[nbh * 8 + 2 + u];
                        float zf = acc[mt][nbh * 4 + 2][r2 * 2 + u] + bsv[nbh * 8 + 4 + u];
                        float zo = acc[mt][nbh * 4 + 3][r2 * 2 + u] + bsv[nbh * 8 + 6 + u];
                        const int ci = idx * 2 + u;
                        float cn = cst[ci] * sigf(zf) + sigf(zi) * tanh_fast(zj);
                        cst[ci] = cn;
                        float h = tanh_fast(cn) * sigf(zo);
                        hp[u] = pack_hl(h);
                    }
                    const int m  = mi * 32 + mt * 16 + gid + 8 * r2;
                    const int h0 = ni * 16 + nbh * 8 + tig * 2;
                    *(uint2*)&g_pipe[g][l][t][m * HH + h0] = make_uint2(hp[0], hp[1]);
                    hAhi[idx] = __byte_perm(hp[0], hp[1], 0x5410);
                    hAlo[idx] = __byte_perm(hp[0], hp[1], 0x7632);
                }

        __syncthreads();   // all warps' GEMM smem reads complete

        // own-h recurrence into A (k = kown + h)
        #pragma unroll
        for (int mt = 0; mt < 2; mt++)
            #pragma unroll
            for (int r2 = 0; r2 < 2; r2++)
                #pragma unroll
                for (int nbh = 0; nbh < 2; nbh++) {
                    const int idx = mt * 4 + r2 * 2 + nbh;
                    const int m = mi * 32 + mt * 16 + gid + 8 * r2;
                    const int c = kown8 + ni * 2 + nbh;
                    unsigned o = (unsigned)(m * 256 + ((c ^ (m & 7)) << 4) + tig * 4);
                    *(unsigned*)(smem + SM_A_HI + o) = hAhi[idx];
                    *(unsigned*)(smem + SM_A_LO + o) = hAlo[idx];
                }

        __threadfence();
        __syncthreads();
        if (tid == 0) g_flag[g][l][t] = 1;   // release
    }
}

// ---------------------------------------------------------------------------
__global__ void dense_k(const float* __restrict__ labels,
                        const float* __restrict__ Wd,
                        const float* __restrict__ bd,
                        float* __restrict__ out, int out_size) {
    __shared__ float red[128];
    int t = blockIdx.x;
    int b = threadIdx.x;   // 0..127
    int g = b >> 6, bl_ = b & 63;
    const unsigned* ht = &g_pipe[g][TT - 1][t][bl_ * HH];
    float s = bd[t];
    #pragma unroll
    for (int h = 0; h < HH; h++)
        s += unpk(ht[h]) * __ldg(&Wd[t * HH + h]);
    float pred = fmaxf(s, 0.f);
    int oi = b * TT + t;
    if (oi < out_size) out[oi] = pred;
    float d = labels[oi] - pred;
    red[b] = d * d;
    __syncthreads();
    #pragma unroll
    for (int s2 = 64; s2 > 0; s2 >>= 1) {
        if (b < s2) red[b] += red[b + s2];
        __syncthreads();
    }
    if (b == 0) g_part[t] = red[0];
}

__global__ void loss_k(float* __restrict__ out, int out_size) {
    __shared__ float red[TT];
    int t = threadIdx.x;
    red[t] = g_part[t];
    __syncthreads();
    #pragma unroll
    for (int s = 32; s > 0; s >>= 1) {
        if (t < s) red[t] += red[t + s];
        __syncthreads();
    }
    if (t == 0 && out_size > BFULL * TT)
        out[BFULL * TT] = red[0] / (float)(BFULL * TT);
}

// ---------------------------------------------------------------------------
extern "C" void kernel_launch(void* const* d_in, const int* in_sizes, int n_in,
                              void* d_out, int out_size) {
    const float* x      = (const float*)d_in[0];
    const float* labels = (const float*)d_in[1];
    const float* W0     = (const float*)d_in[2];
    const float* b0     = (const float*)d_in[3];
    const float* Wl     = (const float*)d_in[4];
    const float* bl     = (const float*)d_in[5];
    const float* Wd     = (const float*)d_in[6];
    const float* bd     = (const float*)d_in[7];
    float* out = (float*)d_out;

    cudaFuncSetAttribute(lstm_hmma,
                         cudaFuncAttributeMaxDynamicSharedMemorySize, SMEM_BYTES);

    zero_k<<<(GG * TT * TT + 255) / 256, 256>>>();
    lstm_hmma<<<GG * TT, NT, SMEM_BYTES>>>(x, W0, b0, Wl, bl);
    dense_k<<<TT, 128>>>(labels, Wd, bd, out, out_size);
    loss_k<<<1, TT>>>(out, out_size);
}

// round 15
// speedup vs baseline: 3.1415x; 1.1500x over previous
#include <cuda_runtime.h>
#include <cuda_fp16.h>
#include <cstdint>

// ---------------------------------------------------------------------------
// TSModel: 64-layer stacked LSTM, T=64, B=128, H=64.
// 2 batch-groups x 64 layers = 128 persistent CTAs. Cell GEMM z[64][256] =
// A[64][128] @ W^T via mma.sync m16n8k16 (f16 in, f32 acc), 3-product fp16
// hi/lo split. K-split overlap: own-h half of the GEMM is issued before the
// flag wait, hiding the h_in handoff. Per-warp release/acquire flags replace
// the CTA-wide threadfence; h is released before the producer's A-write tail.
// ---------------------------------------------------------------------------

#define TT     64
#define BFULL  128
#define HH     64
#define GG     2
#define BG     64
#define N4H    256
#define NT     256

// smem: A_hi/A_lo 64x128 fp16 (16KB each), W_hi/W_lo 256x128 fp16 (64KB each)
#define SM_A_HI   0
#define SM_A_LO   16384
#define SM_W_HI   32768
#define SM_W_LO   98304
#define SM_BIAS   163840
#define SMEM_BYTES 164864

// [g][layer][t][m*64+h], element = packed u32: low16 = fp16 hi, high16 = lo
__device__ unsigned      g_pipe[GG][TT][TT][BG * HH];
__device__ int           g_flagw[GG][TT][TT][8];   // per-producer-warp flags
__device__ float         g_part[TT];

// ---------------------------------------------------------------------------
__device__ __forceinline__ unsigned smem_u32(const void* p) {
    unsigned a;
    asm("{ .reg .u64 t; cvta.to.shared.u64 t, %1; cvt.u32.u64 %0, t; }"
        : "=r"(a) : "l"(p));
    return a;
}
__device__ __forceinline__ float sigf(float x) {
    return __fdividef(1.f, 1.f + __expf(-x));
}
__device__ __forceinline__ float tanh_fast(float x) {
    return __fdividef(2.f, 1.f + __expf(-2.f * x)) - 1.f;
}
__device__ __forceinline__ unsigned pack_hl(float v) {
    __half hi = __float2half_rn(v);
    __half lo = __float2half_rn(v - __half2float(hi));
    return (unsigned)__half_as_ushort(hi) | ((unsigned)__half_as_ushort(lo) << 16);
}
__device__ __forceinline__ float unpk(unsigned v) {
    return __half2float(__ushort_as_half((unsigned short)(v & 0xFFFF))) +
           __half2float(__ushort_as_half((unsigned short)(v >> 16)));
}
// column permutation: original n = g*64+h -> p so that one thread owns all 4
// gates of 4 h-values: p = (h>>4)*64 + ((h>>3)&1)*32 + g*8 + (h&7)
__device__ __host__ __forceinline__ int perm(int n) {
    int g = n >> 6, h = n & 63;
    return ((h >> 4) << 6) + (((h >> 3) & 1) << 5) + (g << 3) + (h & 7);
}
// swizzled tile offset: 256B rows, 16B chunks, chunk ^= row&7
__device__ __forceinline__ unsigned toff(int row, int k) {
    return (unsigned)(row * 256 + ((((k >> 3)) ^ (row & 7)) << 4) + (k & 7) * 2);
}

#define LDSM4(r, a) \
    asm volatile("ldmatrix.sync.aligned.m8n8.x4.shared.b16 {%0,%1,%2,%3}, [%4];" \
                 : "=r"((r)[0]), "=r"((r)[1]), "=r"((r)[2]), "=r"((r)[3]) \
                 : "r"(a))

#define MMA(c, a, b0, b1) \
    asm volatile("mma.sync.aligned.m16n8k16.row.col.f32.f16.f16.f32 " \
                 "{%0,%1,%2,%3},{%4,%5,%6,%7},{%8,%9},{%0,%1,%2,%3};" \
                 : "+f"((c)[0]), "+f"((c)[1]), "+f"((c)[2]), "+f"((c)[3]) \
                 : "r"((a)[0]), "r"((a)[1]), "r"((a)[2]), "r"((a)[3]), \
                   "r"(b0), "r"(b1))

// one K-chunk (k16) of the 3-product split GEMM
#define DO_CHUNK(ks) do {                                                     \
    unsigned af[2][4], wh[4][4], wl_[4][4];                                   \
    const unsigned koA = ((2 * (ks) + aKp) ^ aSw) << 4;                       \
    const unsigned koB = ((2 * (ks) + bKp) ^ bSw) << 4;                       \
    _Pragma("unroll")                                                         \
    for (int mt = 0; mt < 2; mt++) LDSM4(af[mt], aBase[mt] + koA);            \
    _Pragma("unroll")                                                         \
    for (int nb2 = 0; nb2 < 4; nb2++) {                                       \
        LDSM4(wh[nb2],  bBase[nb2] + koB);                                    \
        LDSM4(wl_[nb2], bBase[nb2] + 65536 + koB);                            \
    }                                                                         \
    _Pragma("unroll")                                                         \
    for (int mt = 0; mt < 2; mt++)                                            \
        _Pragma("unroll")                                                     \
        for (int nb2 = 0; nb2 < 4; nb2++) {                                   \
            MMA(acc[mt][2 * nb2],     af[mt], wh[nb2][0],  wh[nb2][1]);       \
            MMA(acc[mt][2 * nb2 + 1], af[mt], wh[nb2][2],  wh[nb2][3]);       \
            MMA(acc[mt][2 * nb2],     af[mt], wl_[nb2][0], wl_[nb2][1]);      \
            MMA(acc[mt][2 * nb2 + 1], af[mt], wl_[nb2][2], wl_[nb2][3]);      \
        }                                                                     \
    _Pragma("unroll")                                                         \
    for (int mt = 0; mt < 2; mt++) LDSM4(af[mt], aBase[mt] + 16384 + koA);    \
    _Pragma("unroll")                                                         \
    for (int mt = 0; mt < 2; mt++)                                            \
        _Pragma("unroll")                                                     \
        for (int nb2 = 0; nb2 < 4; nb2++) {                                   \
            MMA(acc[mt][2 * nb2],     af[mt], wh[nb2][0], wh[nb2][1]);        \
            MMA(acc[mt][2 * nb2 + 1], af[mt], wh[nb2][2], wh[nb2][3]);        \
        }                                                                     \
} while (0)

// ---------------------------------------------------------------------------
__global__ void zero_k() {
    int i = blockIdx.x * blockDim.x + threadIdx.x;
    if (i < GG * TT * TT * 8) ((int*)&g_flagw[0][0][0][0])[i] = 0;
}

// ---------------------------------------------------------------------------
__global__ __launch_bounds__(NT, 1)
void lstm_hmma(const float* __restrict__ x,
               const float* __restrict__ W0, const float* __restrict__ b0,
               const float* __restrict__ Wl, const float* __restrict__ bl) {
    extern __shared__ char smem[];
    const unsigned sb = smem_u32(smem);
    const int l = blockIdx.x & 63, g = blockIdx.x >> 6;
    const int tid = threadIdx.x;
    const int w = tid >> 5, lane = tid & 31;
    const int mi = w >> 2, ni = w & 3;          // warp tile: 32M x 64N
    const int gid = lane >> 2, tig = lane & 3;

    // ---- zero A tiles (and W tiles for l==0, K padding) ----
    {
        int zb = (l == 0) ? SM_BIAS : SM_W_HI;
        for (int i = tid * 16; i < zb; i += NT * 16)
            *(uint4*)(smem + i) = make_uint4(0, 0, 0, 0);
    }
    __syncthreads();

    // ---- weights -> fp16 hi/lo at permuted rows ----
    if (l == 0) {
        // W0[65][256]: row 0 (x) -> k=127; rows 1..64 (h_own) -> k=0..63
        for (int i = tid; i < 65 * N4H; i += NT) {
            int kw = i >> 8, n = i & 255;
            int k = kw ? (kw - 1) : 127;
            int p = perm(n);
            float f = W0[i];
            __half hi = __float2half_rn(f);
            __half lo = __float2half_rn(f - __half2float(hi));
            unsigned o = toff(p, k);
            *(__half*)(smem + SM_W_HI + o) = hi;
            *(__half*)(smem + SM_W_LO + o) = lo;
        }
    } else {
        const float* Ws = Wl + (size_t)(l - 1) * 128 * N4H;
        for (int i = tid; i < 128 * N4H; i += NT) {
            int k = i >> 8, n = i & 255;       // k: 0..63 h_in, 64..127 h_own
            int p = perm(n);
            float f = Ws[i];
            __half hi = __float2half_rn(f);
            __half lo = __float2half_rn(f - __half2float(hi));
            unsigned o = toff(p, k);
            *(__half*)(smem + SM_W_HI + o) = hi;
            *(__half*)(smem + SM_W_LO + o) = lo;
        }
    }
    {
        const float* bs = (l == 0) ? b0 : (bl + (size_t)(l - 1) * N4H);
        if (tid < N4H) *(float*)(smem + SM_BIAS + perm(tid) * 4) = bs[tid];
    }
    __syncthreads();

    // ---- ldmatrix per-lane address bases ----
    const unsigned aRow = (lane & 7) | (lane & 8);         // 0..15
    const unsigned aKp  = (lane >> 4) & 1;                 // +8k chunk
    const unsigned aSw  = aRow & 7;
    const unsigned bRow = (lane & 7) | ((lane & 16) >> 1); // 0..15
    const unsigned bKp  = (lane >> 3) & 1;
    const unsigned bSw  = bRow & 7;
    unsigned aBase[2], bBase[4];
    #pragma unroll
    for (int mt = 0; mt < 2; mt++)
        aBase[mt] = sb + SM_A_HI + (mi * 32 + mt * 16 + aRow) * 256;
    #pragma unroll
    for (int nb2 = 0; nb2 < 4; nb2++)
        bBase[nb2] = sb + SM_W_HI + (ni * 64 + nb2 * 16 + bRow) * 256;

    // ---- bias regs: bsv[nbh*8 + g*2 + u] ----
    float bsv[16];
    #pragma unroll
    for (int i = 0; i < 16; i++) {
        int nbh = i >> 3, gg = (i >> 1) & 3, u = i & 1;
        bsv[i] = *(float*)(smem + SM_BIAS +
                           (ni * 64 + nbh * 32 + gg * 8 + tig * 2 + u) * 4);
    }

    // early chunks = own-h (ready in smem); late chunks = h_in / x
    const int earlyBase = (l == 0) ? 0 : 4;
    const int lateBase  = (l == 0) ? 4 : 0;
    const int kown8     = (l == 0) ? 0 : 8;   // own-h chunk base (k/8)

    float cst[16];
    #pragma unroll
    for (int i = 0; i < 16; i++) cst[i] = 0.f;

    float xv = 0.f;
    if (l == 0 && tid < BG) xv = x[(size_t)(g * BG + tid) * TT];

    for (int t = 0; t < TT; t++) {
        float acc[2][8][4];
        #pragma unroll
        for (int a2 = 0; a2 < 2; a2++)
            #pragma unroll
            for (int b2 = 0; b2 < 8; b2++)
                #pragma unroll
                for (int r2 = 0; r2 < 4; r2++) acc[a2][b2][r2] = 0.f;

        // ---- early half: own-h chunks (A already in smem) ----
        #pragma unroll
        for (int kk = 0; kk < 4; kk++) DO_CHUNK(earlyBase + kk);

        // ---- acquire + fill late A half ----
        if (l > 0) {
            if (tid < 8) {
                const int* fp = &g_flagw[g][l - 1][t][tid];
                int fv;
                do {
                    asm volatile("ld.acquire.gpu.b32 %0, [%1];"
                                 : "=r"(fv) : "l"(fp) : "memory");
                } while (fv == 0);
            }
            __syncthreads();
            const int m = tid >> 2, q = tid & 3;   // 16 cols per thread
            const uint4* src = (const uint4*)&g_pipe[g][l - 1][t][m * HH + q * 16];
            uint4 e[4];
            #pragma unroll
            for (int u = 0; u < 4; u++) e[u] = src[u];
            #pragma unroll
            for (int u = 0; u < 2; u++) {
                uint4 a = e[2 * u], b2 = e[2 * u + 1];
                uint4 hi4 = make_uint4(__byte_perm(a.x, a.y, 0x5410),
                                       __byte_perm(a.z, a.w, 0x5410),
                                       __byte_perm(b2.x, b2.y, 0x5410),
                                       __byte_perm(b2.z, b2.w, 0x5410));
                uint4 lo4 = make_uint4(__byte_perm(a.x, a.y, 0x7632),
                                       __byte_perm(a.z, a.w, 0x7632),
                                       __byte_perm(b2.x, b2.y, 0x7632),
                                       __byte_perm(b2.z, b2.w, 0x7632));
                int c = q * 2 + u;                     // h_in at k=0..63
                unsigned o = (unsigned)(m * 256 + ((c ^ (m & 7)) << 4));
                *(uint4*)(smem + SM_A_HI + o) = hi4;
                *(uint4*)(smem + SM_A_LO + o) = lo4;
            }
        } else {
            if (tid < BG) {
                __half hi = __float2half_rn(xv);
                __half lo = __float2half_rn(xv - __half2float(hi));
                unsigned o = toff(tid, 127);           // x at k=127
                *(__half*)(smem + SM_A_HI + o) = hi;
                *(__half*)(smem + SM_A_LO + o) = lo;
                if (t + 1 < TT) xv = x[(size_t)(g * BG + tid) * TT + t + 1];
            }
        }
        __syncthreads();

        // ---- late half: h_in / x chunks ----
        #pragma unroll
        for (int kk = 0; kk < 4; kk++) DO_CHUNK(lateBase + kk);

        // ---- epilogue: gates from register accumulators ----
        unsigned hAhi[8], hAlo[8];
        #pragma unroll
        for (int mt = 0; mt < 2; mt++)
            #pragma unroll
            for (int r2 = 0; r2 < 2; r2++)
                #pragma unroll
                for (int nbh = 0; nbh < 2; nbh++) {
                    const int idx = mt * 4 + r2 * 2 + nbh;
                    unsigned hp[2];
                    #pragma unroll
                    for (int u = 0; u < 2; u++) {
                        float zi = acc[mt][nbh * 4 + 0][r2 * 2 + u] + bsv[nbh * 8 + 0 + u];
                        float zj = acc[mt][nbh * 4 + 1][r2 * 2 + u] + bsv[nbh * 8 + 2 + u];
                        float zf = acc[mt][nbh * 4 + 2][r2 * 2 + u] + bsv[nbh * 8 + 4 + u];
                        float zo = acc[mt][nbh * 4 + 3][r2 * 2 + u] + bsv[nbh * 8 + 6 + u];
                        const int ci = idx * 2 + u;
                        float cn = cst[ci] * sigf(zf) + sigf(zi) * tanh_fast(zj);
                        cst[ci] = cn;
                        float h = tanh_fast(cn) * sigf(zo);
                        hp[u] = pack_hl(h);
                    }
                    const int m  = mi * 32 + mt * 16 + gid + 8 * r2;
                    const int h0 = ni * 16 + nbh * 8 + tig * 2;
                    *(uint2*)&g_pipe[g][l][t][m * HH + h0] = make_uint2(hp[0], hp[1]);
                    hAhi[idx] = __byte_perm(hp[0], hp[1], 0x5410);
                    hAlo[idx] = __byte_perm(hp[0], hp[1], 0x7632);
                }

        // early per-warp release: this warp's h slice is published
        __syncwarp();
        if (lane == 0)
            asm volatile("st.release.gpu.b32 [%0], %1;"
                         :: "l"(&g_flagw[g][l][t][w]), "r"(1) : "memory");

        __syncthreads();   // all warps' GEMM smem reads complete

        // own-h recurrence into A (k = kown + h)
        #pragma unroll
        for (int mt = 0; mt < 2; mt++)
            #pragma unroll
            for (int r2 = 0; r2 < 2; r2++)
                #pragma unroll
                for (int nbh = 0; nbh < 2; nbh++) {
                    const int idx = mt * 4 + r2 * 2 + nbh;
                    const int m = mi * 32 + mt * 16 + gid + 8 * r2;
                    const int c = kown8 + ni * 2 + nbh;
                    unsigned o = (unsigned)(m * 256 + ((c ^ (m & 7)) << 4) + tig * 4);
                    *(unsigned*)(smem + SM_A_HI + o) = hAhi[idx];
                    *(unsigned*)(smem + SM_A_LO + o) = hAlo[idx];
                }

        __syncthreads();   // A own-half visible for next t's early chunks
    }
}

// ---------------------------------------------------------------------------
__global__ void dense_k(const float* __restrict__ labels,
                        const float* __restrict__ Wd,
                        const float* __restrict__ bd,
                        float* __restrict__ out, int out_size) {
    __shared__ float red[128];
    int t = blockIdx.x;
    int b = threadIdx.x;   // 0..127
    int g = b >> 6, bl_ = b & 63;
    const unsigned* ht = &g_pipe[g][TT - 1][t][bl_ * HH];
    float s = bd[t];
    #pragma unroll
    for (int h = 0; h < HH; h++)
        s += unpk(ht[h]) * __ldg(&Wd[t * HH + h]);
    float pred = fmaxf(s, 0.f);
    int oi = b * TT + t;
    if (oi < out_size) out[oi] = pred;
    float d = labels[oi] - pred;
    red[b] = d * d;
    __syncthreads();
    #pragma unroll
    for (int s2 = 64; s2 > 0; s2 >>= 1) {
        if (b < s2) red[b] += red[b + s2];
        __syncthreads();
    }
    if (b == 0) g_part[t] = red[0];
}

__global__ void loss_k(float* __restrict__ out, int out_size) {
    __shared__ float red[TT];
    int t = threadIdx.x;
    red[t] = g_part[t];
    __syncthreads();
    #pragma unroll
    for (int s = 32; s > 0; s >>= 1) {
        if (t < s) red[t] += red[t + s];
        __syncthreads();
    }
    if (t == 0 && out_size > BFULL * TT)
        out[BFULL * TT] = red[0] / (float)(BFULL * TT);
}

// ---------------------------------------------------------------------------
extern "C" void kernel_launch(void* const* d_in, const int* in_sizes, int n_in,
                              void* d_out, int out_size) {
    const float* x      = (const float*)d_in[0];
    const float* labels = (const float*)d_in[1];
    const float* W0     = (const float*)d_in[2];
    const float* b0     = (const float*)d_in[3];
    const float* Wl     = (const float*)d_in[4];
    const float* bl     = (const float*)d_in[5];
    const float* Wd     = (const float*)d_in[6];
    const float* bd     = (const float*)d_in[7];
    float* out = (float*)d_out;

    cudaFuncSetAttribute(lstm_hmma,
                         cudaFuncAttributeMaxDynamicSharedMemorySize, SMEM_BYTES);

    zero_k<<<(GG * TT * TT * 8 + 255) / 256, 256>>>();
    lstm_hmma<<<GG * TT, NT, SMEM_BYTES>>>(x, W0, b0, Wl, bl);
    dense_k<<<TT, 128>>>(labels, Wd, bd, out, out_size);
    loss_k<<<1, TT>>>(out, out_size);
}

// round 17
// speedup vs baseline: 3.4198x; 1.0886x over previous
#include <cuda_runtime.h>
#include <cuda_fp16.h>
#include <cstdint>

// ---------------------------------------------------------------------------
// TSModel: 64-layer stacked LSTM, T=64, B=128, H=64.
// 2 batch-groups x 64 layers = 128 persistent CTAs. Cell GEMM z[64][256] =
// A[64][128] @ W^T via mma.sync m16n8k16 (f16 in, f32 acc), 3-product fp16
// hi/lo split. K-split overlap hides the h_in handoff behind the own-h half
// of the GEMM. Double-buffered A tile (2 barriers/step). Per-warp producer
// flags acquired at THREAD granularity (each fill thread needs exactly one
// producer quadrant). 8-MUFU epilogue via shared reciprocals.
// ---------------------------------------------------------------------------

#define TT     64
#define BFULL  128
#define HH     64
#define GG     2
#define BG     64
#define N4H    256
#define NT     256

// smem: A bufs 2x(hi+lo) 64x128 fp16 (16KB each); W_hi/W_lo 256x128 (64KB each)
#define SM_A_HI   0          // +bufOff (0 or 32768); lo at +16384
#define SM_W_HI   65536
#define SM_W_LO   131072
#define SM_BIAS   196608
#define SMEM_BYTES 197632

// [g][layer][t][m*64+h], element = packed u32: low16 = fp16 hi, high16 = lo
__device__ unsigned      g_pipe[GG][TT][TT][BG * HH];
__device__ int           g_flagw[GG][TT][TT][8];   // per-producer-warp flags
__device__ float         g_part[TT];

// ---------------------------------------------------------------------------
__device__ __forceinline__ unsigned smem_u32(const void* p) {
    unsigned a;
    asm("{ .reg .u64 t; cvta.to.shared.u64 t, %1; cvt.u32.u64 %0, t; }"
        : "=r"(a) : "l"(p));
    return a;
}
__device__ __forceinline__ float rcpa(float x) {
    float r;
    asm("rcp.approx.f32 %0, %1;" : "=f"(r) : "f"(x));
    return r;
}
__device__ __forceinline__ unsigned pack_hl(float v) {
    __half hi = __float2half_rn(v);
    __half lo = __float2half_rn(v - __half2float(hi));
    return (unsigned)__half_as_ushort(hi) | ((unsigned)__half_as_ushort(lo) << 16);
}
__device__ __forceinline__ float unpk(unsigned v) {
    return __half2float(__ushort_as_half((unsigned short)(v & 0xFFFF))) +
           __half2float(__ushort_as_half((unsigned short)(v >> 16)));
}
// column permutation: original n = g*64+h -> p so that one thread owns all 4
// gates of 4 h-values: p = (h>>4)*64 + ((h>>3)&1)*32 + g*8 + (h&7)
__device__ __host__ __forceinline__ int perm(int n) {
    int g = n >> 6, h = n & 63;
    return ((h >> 4) << 6) + (((h >> 3) & 1) << 5) + (g << 3) + (h & 7);
}
// swizzled tile offset: 256B rows, 16B chunks, chunk ^= row&7
__device__ __forceinline__ unsigned toff(int row, int k) {
    return (unsigned)(row * 256 + ((((k >> 3)) ^ (row & 7)) << 4) + (k & 7) * 2);
}

#define LDSM4(r, a) \
    asm volatile("ldmatrix.sync.aligned.m8n8.x4.shared.b16 {%0,%1,%2,%3}, [%4];" \
                 : "=r"((r)[0]), "=r"((r)[1]), "=r"((r)[2]), "=r"((r)[3]) \
                 : "r"(a))

#define MMA(c, a, b0, b1) \
    asm volatile("mma.sync.aligned.m16n8k16.row.col.f32.f16.f16.f32 " \
                 "{%0,%1,%2,%3},{%4,%5,%6,%7},{%8,%9},{%0,%1,%2,%3};" \
                 : "+f"((c)[0]), "+f"((c)[1]), "+f"((c)[2]), "+f"((c)[3]) \
                 : "r"((a)[0]), "r"((a)[1]), "r"((a)[2]), "r"((a)[3]), \
                   "r"(b0), "r"(b1))

// one K-chunk (k16) of the 3-product split GEMM; A addressed via bufOff
#define DO_CHUNK(ks) do {                                                     \
    unsigned af[2][4], wh[4][4], wl_[4][4];                                   \
    const unsigned koA = ((2 * (ks) + aKp) ^ aSw) << 4;                       \
    const unsigned koB = ((2 * (ks) + bKp) ^ bSw) << 4;                       \
    _Pragma("unroll")                                                         \
    for (int mt = 0; mt < 2; mt++) LDSM4(af[mt], aBase[mt] + bufOff + koA);   \
    _Pragma("unroll")                                                         \
    for (int nb2 = 0; nb2 < 4; nb2++) {                                       \
        LDSM4(wh[nb2],  bBase[nb2] + koB);                                    \
        LDSM4(wl_[nb2], bBase[nb2] + 65536 + koB);                            \
    }                                                                         \
    _Pragma("unroll")                                                         \
    for (int mt = 0; mt < 2; mt++)                                            \
        _Pragma("unroll")                                                     \
        for (int nb2 = 0; nb2 < 4; nb2++) {                                   \
            MMA(acc[mt][2 * nb2],     af[mt], wh[nb2][0],  wh[nb2][1]);       \
            MMA(acc[mt][2 * nb2 + 1], af[mt], wh[nb2][2],  wh[nb2][3]);       \
            MMA(acc[mt][2 * nb2],     af[mt], wl_[nb2][0], wl_[nb2][1]);      \
            MMA(acc[mt][2 * nb2 + 1], af[mt], wl_[nb2][2], wl_[nb2][3]);      \
        }                                                                     \
    _Pragma("unroll")                                                         \
    for (int mt = 0; mt < 2; mt++)                                            \
        LDSM4(af[mt], aBase[mt] + bufOff + 16384 + koA);                      \
    _Pragma("unroll")                                                         \
    for (int mt = 0; mt < 2; mt++)                                            \
        _Pragma("unroll")                                                     \
        for (int nb2 = 0; nb2 < 4; nb2++) {                                   \
            MMA(acc[mt][2 * nb2],     af[mt], wh[nb2][0], wh[nb2][1]);        \
            MMA(acc[mt][2 * nb2 + 1], af[mt], wh[nb2][2], wh[nb2][3]);        \
        }                                                                     \
} while (0)

// ---------------------------------------------------------------------------
__global__ void zero_k() {
    int i = blockIdx.x * blockDim.x + threadIdx.x;
    if (i < GG * TT * TT * 8) ((int*)&g_flagw[0][0][0][0])[i] = 0;
}

// ---------------------------------------------------------------------------
__global__ __launch_bounds__(NT, 1)
void lstm_hmma(const float* __restrict__ x,
               const float* __restrict__ W0, const float* __restrict__ b0,
               const float* __restrict__ Wl, const float* __restrict__ bl) {
    extern __shared__ char smem[];
    const unsigned sb = smem_u32(smem);
    const int l = blockIdx.x & 63, g = blockIdx.x >> 6;
    const int tid = threadIdx.x;
    const int w = tid >> 5, lane = tid & 31;
    const int mi = w >> 2, ni = w & 3;          // warp tile: 32M x 64N
    const int gid = lane >> 2, tig = lane & 3;

    // ---- zero both A buffers (and W tiles for l==0, K padding) ----
    {
        int zb = (l == 0) ? SM_BIAS : SM_W_HI;
        for (int i = tid * 16; i < zb; i += NT * 16)
            *(uint4*)(smem + i) = make_uint4(0, 0, 0, 0);
    }
    __syncthreads();

    // ---- weights -> fp16 hi/lo at permuted rows ----
    if (l == 0) {
        // W0[65][256]: row 0 (x) -> k=127; rows 1..64 (h_own) -> k=0..63
        for (int i = tid; i < 65 * N4H; i += NT) {
            int kw = i >> 8, n = i & 255;
            int k = kw ? (kw - 1) : 127;
            int p = perm(n);
            float f = W0[i];
            __half hi = __float2half_rn(f);
            __half lo = __float2half_rn(f - __half2float(hi));
            unsigned o = toff(p, k);
            *(__half*)(smem + SM_W_HI + o) = hi;
            *(__half*)(smem + SM_W_LO + o) = lo;
        }
    } else {
        const float* Ws = Wl + (size_t)(l - 1) * 128 * N4H;
        for (int i = tid; i < 128 * N4H; i += NT) {
            int k = i >> 8, n = i & 255;       // k: 0..63 h_in, 64..127 h_own
            int p = perm(n);
            float f = Ws[i];
            __half hi = __float2half_rn(f);
            __half lo = __float2half_rn(f - __half2float(hi));
            unsigned o = toff(p, k);
            *(__half*)(smem + SM_W_HI + o) = hi;
            *(__half*)(smem + SM_W_LO + o) = lo;
        }
    }
    {
        const float* bs = (l == 0) ? b0 : (bl + (size_t)(l - 1) * N4H);
        if (tid < N4H) *(float*)(smem + SM_BIAS + perm(tid) * 4) = bs[tid];
    }
    __syncthreads();

    // ---- ldmatrix per-lane address bases ----
    const unsigned aRow = (lane & 7) | (lane & 8);         // 0..15
    const unsigned aKp  = (lane >> 4) & 1;                 // +8k chunk
    const unsigned aSw  = aRow & 7;
    const unsigned bRow = (lane & 7) | ((lane & 16) >> 1); // 0..15
    const unsigned bKp  = (lane >> 3) & 1;
    const unsigned bSw  = bRow & 7;
    unsigned aBase[2], bBase[4];
    #pragma unroll
    for (int mt = 0; mt < 2; mt++)
        aBase[mt] = sb + SM_A_HI + (mi * 32 + mt * 16 + aRow) * 256;
    #pragma unroll
    for (int nb2 = 0; nb2 < 4; nb2++)
        bBase[nb2] = sb + SM_W_HI + (ni * 64 + nb2 * 16 + bRow) * 256;

    // ---- bias regs: bsv[nbh*8 + g*2 + u] ----
    float bsv[16];
    #pragma unroll
    for (int i = 0; i < 16; i++) {
        int nbh = i >> 3, gg = (i >> 1) & 3, u = i & 1;
        bsv[i] = *(float*)(smem + SM_BIAS +
                           (ni * 64 + nbh * 32 + gg * 8 + tig * 2 + u) * 4);
    }

    // early chunks = own-h (ready in smem); late chunks = h_in / x
    const int earlyBase = (l == 0) ? 0 : 4;
    const int lateBase  = (l == 0) ? 4 : 0;
    const int kown8     = (l == 0) ? 0 : 8;   // own-h chunk base (k/8)

    // fill mapping: this thread fills row m, h cols q*16..q*16+15 ->
    // produced by exactly one upstream warp: (m>>5)*4 + q
    const int fm = tid >> 2, fq = tid & 3;
    const int upw = ((fm >> 5) << 2) | fq;

    float cst[16];
    #pragma unroll
    for (int i = 0; i < 16; i++) cst[i] = 0.f;

    float xv = 0.f;
    if (l == 0 && tid < BG) xv = x[(size_t)(g * BG + tid) * TT];

    for (int t = 0; t < TT; t++) {
        const unsigned bufOff  = (unsigned)(t & 1) * 32768;
        const unsigned bufOffN = (unsigned)(~t & 1) * 32768;

        float acc[2][8][4];
        #pragma unroll
        for (int a2 = 0; a2 < 2; a2++)
            #pragma unroll
            for (int b2 = 0; b2 < 8; b2++)
                #pragma unroll
                for (int r2 = 0; r2 < 4; r2++) acc[a2][b2][r2] = 0.f;

        // ---- early half: own-h chunks (A already in smem) ----
        #pragma unroll
        for (int kk = 0; kk < 4; kk++) DO_CHUNK(earlyBase + kk);

        // ---- acquire (per-thread, one producer quadrant) + fill late A ----
        if (l > 0) {
            {
                const int* fp = &g_flagw[g][l - 1][t][upw];
                int fv;
                do {
                    asm volatile("ld.acquire.gpu.b32 %0, [%1];"
                                 : "=r"(fv) : "l"(fp) : "memory");
                } while (fv == 0);
            }
            const uint4* src = (const uint4*)&g_pipe[g][l - 1][t][fm * HH + fq * 16];
            uint4 e[4];
            #pragma unroll
            for (int u = 0; u < 4; u++) e[u] = src[u];
            #pragma unroll
            for (int u = 0; u < 2; u++) {
                uint4 a = e[2 * u], b2 = e[2 * u + 1];
                uint4 hi4 = make_uint4(__byte_perm(a.x, a.y, 0x5410),
                                       __byte_perm(a.z, a.w, 0x5410),
                                       __byte_perm(b2.x, b2.y, 0x5410),
                                       __byte_perm(b2.z, b2.w, 0x5410));
                uint4 lo4 = make_uint4(__byte_perm(a.x, a.y, 0x7632),
                                       __byte_perm(a.z, a.w, 0x7632),
                                       __byte_perm(b2.x, b2.y, 0x7632),
                                       __byte_perm(b2.z, b2.w, 0x7632));
                int c = fq * 2 + u;                    // h_in at k=0..63
                unsigned o = (unsigned)(fm * 256 + ((c ^ (fm & 7)) << 4));
                *(uint4*)(smem + bufOff + SM_A_HI + o) = hi4;
                *(uint4*)(smem + bufOff + SM_A_HI + 16384 + o) = lo4;
            }
        } else {
            if (tid < BG) {
                __half hi = __float2half_rn(xv);
                __half lo = __float2half_rn(xv - __half2float(hi));
                unsigned o = toff(tid, 127);           // x at k=127
                *(__half*)(smem + bufOff + SM_A_HI + o) = hi;
                *(__half*)(smem + bufOff + SM_A_HI + 16384 + o) = lo;
                if (t + 1 < TT) xv = x[(size_t)(g * BG + tid) * TT + t + 1];
            }
        }
        __syncthreads();

        // ---- late half: h_in / x chunks ----
        #pragma unroll
        for (int kk = 0; kk < 4; kk++) DO_CHUNK(lateBase + kk);

        // ---- epilogue: gates from register accumulators (8 MUFU/cell) ----
        unsigned hAhi[8], hAlo[8];
        #pragma unroll
        for (int mt = 0; mt < 2; mt++)
            #pragma unroll
            for (int r2 = 0; r2 < 2; r2++)
                #pragma unroll
                for (int nbh = 0; nbh < 2; nbh++) {
                    const int idx = mt * 4 + r2 * 2 + nbh;
                    unsigned hp[2];
                    #pragma unroll
                    for (int u = 0; u < 2; u++) {
                        float zi = acc[mt][nbh * 4 + 0][r2 * 2 + u] + bsv[nbh * 8 + 0 + u];
                        float zj = acc[mt][nbh * 4 + 1][r2 * 2 + u] + bsv[nbh * 8 + 2 + u];
                        float zf = acc[mt][nbh * 4 + 2][r2 * 2 + u] + bsv[nbh * 8 + 4 + u];
                        float zo = acc[mt][nbh * 4 + 3][r2 * 2 + u] + bsv[nbh * 8 + 6 + u];
                        const int ci = idx * 2 + u;
                        float ei = __expf(-zi);
                        float ej = __expf(2.f * zj);
                        float ef = __expf(-zf);
                        float eo = __expf(-zo);
                        // c*sig(f) + sig(i)*tanh(j), shared-rcp form
                        float cn = cst[ci] * rcpa(1.f + ef) +
                                   (ej - 1.f) * rcpa((1.f + ei) * (ej + 1.f));
                        cst[ci] = cn;
                        float ec = __expf(2.f * cn);
                        // tanh(c)*sig(o), shared-rcp form
                        float h = (ec - 1.f) * rcpa((ec + 1.f) * (1.f + eo));
                        hp[u] = pack_hl(h);
                    }
                    const int m  = mi * 32 + mt * 16 + gid + 8 * r2;
                    const int h0 = ni * 16 + nbh * 8 + tig * 2;
                    *(uint2*)&g_pipe[g][l][t][m * HH + h0] = make_uint2(hp[0], hp[1]);
                    hAhi[idx] = __byte_perm(hp[0], hp[1], 0x5410);
                    hAlo[idx] = __byte_perm(hp[0], hp[1], 0x7632);
                }

        // early per-warp release: this warp's h quadrant is published
        __syncwarp();
        if (lane == 0)
            asm volatile("st.release.gpu.b32 [%0], %1;"
                         :: "l"(&g_flagw[g][l][t][w]), "r"(1) : "memory");

        // own-h recurrence into the OTHER A buffer (k = kown + h)
        #pragma unroll
        for (int mt = 0; mt < 2; mt++)
            #pragma unroll
            for (int r2 = 0; r2 < 2; r2++)
                #pragma unroll
                for (int nbh = 0; nbh < 2; nbh++) {
                    const int idx = mt * 4 + r2 * 2 + nbh;
                    const int m = mi * 32 + mt * 16 + gid + 8 * r2;
                    const int c = kown8 + ni * 2 + nbh;
                    unsigned o = (unsigned)(m * 256 + ((c ^ (m & 7)) << 4) + tig * 4);
                    *(unsigned*)(smem + bufOffN + SM_A_HI + o) = hAhi[idx];
                    *(unsigned*)(smem + bufOffN + SM_A_HI + 16384 + o) = hAlo[idx];
                }

        __syncthreads();   // A own-half visible for next t's early chunks
    }
}

// ---------------------------------------------------------------------------
__global__ void dense_k(const float* __restrict__ labels,
                        const float* __restrict__ Wd,
                        const float* __restrict__ bd,
                        float* __restrict__ out, int out_size) {
    __shared__ float red[128];
    int t = blockIdx.x;
    int b = threadIdx.x;   // 0..127
    int g = b >> 6, bl_ = b & 63;
    const unsigned* ht = &g_pipe[g][TT - 1][t][bl_ * HH];
    float s = bd[t];
    #pragma unroll
    for (int h = 0; h < HH; h++)
        s += unpk(ht[h]) * __ldg(&Wd[t * HH + h]);
    float pred = fmaxf(s, 0.f);
    int oi = b * TT + t;
    if (oi < out_size) out[oi] = pred;
    float d = labels[oi] - pred;
    red[b] = d * d;
    __syncthreads();
    #pragma unroll
    for (int s2 = 64; s2 > 0; s2 >>= 1) {
        if (b < s2) red[b] += red[b + s2];
        __syncthreads();
    }
    if (b == 0) g_part[t] = red[0];
}

__global__ void loss_k(float* __restrict__ out, int out_size) {
    __shared__ float red[TT];
    int t = threadIdx.x;
    red[t] = g_part[t];
    __syncthreads();
    #pragma unroll
    for (int s = 32; s > 0; s >>= 1) {
        if (t < s) red[t] += red[t + s];
        __syncthreads();
    }
    if (t == 0 && out_size > BFULL * TT)
        out[BFULL * TT] = red[0] / (float)(BFULL * TT);
}

// ---------------------------------------------------------------------------
extern "C" void kernel_launch(void* const* d_in, const int* in_sizes, int n_in,
                              void* d_out, int out_size) {
    const float* x      = (const float*)d_in[0];
    const float* labels = (const float*)d_in[1];
    const float* W0     = (const float*)d_in[2];
    const float* b0     = (const float*)d_in[3];
    const float* Wl     = (const float*)d_in[4];
    const float* bl     = (const float*)d_in[5];
    const float* Wd     = (const float*)d_in[6];
    const float* bd     = (const float*)d_in[7];
    float* out = (float*)d_out;

    cudaFuncSetAttribute(lstm_hmma,
                         cudaFuncAttributeMaxDynamicSharedMemorySize, SMEM_BYTES);

    zero_k<<<(GG * TT * TT * 8 + 255) / 256, 256>>>();
    lstm_hmma<<<GG * TT, NT, SMEM_BYTES>>>(x, W0, b0, Wl, bl);
    dense_k<<<TT, 128>>>(labels, Wd, bd, out, out_size);
    loss_k<<<1, TT>>>(out, out_size);
}